// round 12
// baseline (speedup 1.0000x reference)
#include <cuda_runtime.h>
#include <cuda.h>

#define NS      32768
#define NT      512
#define SEASK   24
#define LEVW    512
#define SEAW    536
#define LOGW    511

#define NWARP   32          // series per block
#define BLOCK   96          // W0 recurrence | W1a logs/gd lo + y prefetch | W1b logs/gd hi + TMA
#define NPER    21
#define YSTR    28          // ybuf row stride (conflict-free .128)
#define TSTR    24          // TMA tile row stride (packed, required by TMA)
#define ASTR    28          // atile row stride (padded, conflict-free)
#define DSTR    28          // dtile row stride

__device__ __forceinline__ unsigned smem_u32(const void* p) {
    return (unsigned)__cvta_generic_to_shared(p);
}
__device__ __forceinline__ void cp16(unsigned dst, const void* src) {
    asm volatile("cp.async.cg.shared.global [%0], [%1], 16;\n" :: "r"(dst), "l"(src) : "memory");
}
__device__ __forceinline__ void cp_commit() {
    asm volatile("cp.async.commit_group;\n" ::: "memory");
}
template<int N> __device__ __forceinline__ void cp_wait() {
    asm volatile("cp.async.wait_group %0;\n" :: "n"(N) : "memory");
}
__device__ __forceinline__ void tma_store2d(const void* map, int x, int y, unsigned smem) {
    asm volatile("cp.async.bulk.tensor.2d.global.shared::cta.tile.bulk_group [%0, {%1, %2}], [%3];"
                 :: "l"(map), "r"(x), "r"(y), "r"(smem) : "memory");
}
__device__ __forceinline__ void bulk_commit() {
    asm volatile("cp.async.bulk.commit_group;" ::: "memory");
}
template<int N> __device__ __forceinline__ void bulk_wait() {
    asm volatile("cp.async.bulk.wait_group %0;" :: "n"(N) : "memory");
}
__device__ __forceinline__ void fence_async_shared() {
    asm volatile("fence.proxy.async.shared::cta;" ::: "memory");
}

// 12 steps of the recurrence. Seasonal state carried in smem tiles:
// column k of the previous period's tiles holds the seasonal value / a*recip
// for the exact slot read at column k this period (24-step alignment).
__device__ __forceinline__ void half12(
    const float* __restrict__ ysm, const float* __restrict__ sold,
    const float* __restrict__ aold,
    float* __restrict__ lnew, float* __restrict__ snew, float* __restrict__ anew,
    float a, float oma, float& lev)
{
    float yt[12], q_[12], nl_[12];
    #pragma unroll
    for (int m = 0; m < 3; m++) {
        const float4 v = *(const float4*)(ysm  + 4 * m);
        const float4 w = *(const float4*)(aold + 4 * m);
        yt[4*m+0] = v.x; yt[4*m+1] = v.y; yt[4*m+2] = v.z; yt[4*m+3] = v.w;
        q_[4*m+0] = v.x * w.x; q_[4*m+1] = v.y * w.y;
        q_[4*m+2] = v.z * w.z; q_[4*m+3] = v.w * w.w;
    }
    #pragma unroll
    for (int k = 0; k < 12; k++) { nl_[k] = fmaf(oma, lev, q_[k]); lev = nl_[k]; }
    #pragma unroll
    for (int m = 0; m < 3; m++) {
        const float4 sv4 = *(const float4*)(sold + 4 * m);
        const float n0 = fmaf(a, __fdividef(yt[4*m+0], nl_[4*m+0]), oma * sv4.x);
        const float n1 = fmaf(a, __fdividef(yt[4*m+1], nl_[4*m+1]), oma * sv4.y);
        const float n2 = fmaf(a, __fdividef(yt[4*m+2], nl_[4*m+2]), oma * sv4.z);
        const float n3 = fmaf(a, __fdividef(yt[4*m+3], nl_[4*m+3]), oma * sv4.w);
        *(float4*)(snew + 4*m) = make_float4(n0, n1, n2, n3);
        *(float4*)(anew + 4*m) = make_float4(__fdividef(a, n0), __fdividef(a, n1),
                                             __fdividef(a, n2), __fdividef(a, n3));
        *(float4*)(lnew + 4*m) = make_float4(nl_[4*m+0], nl_[4*m+1], nl_[4*m+2], nl_[4*m+3]);
    }
}

// 12 logs + diffs; returns last log for the carry.
__device__ __forceinline__ float loghalf(const float* __restrict__ nlrow,
                                         float* __restrict__ drow, float llev)
{
    #pragma unroll
    for (int m = 0; m < 3; m++) {
        const float4 v = *(const float4*)(nlrow + 4 * m);
        const float l0 = __logf(v.x), l1 = __logf(v.y), l2 = __logf(v.z), l3 = __logf(v.w);
        *(float4*)(drow + 4 * m) = make_float4(l0 - llev, l1 - l0, l2 - l1, l3 - l2);
        llev = l3;
    }
    return llev;
}

__global__ __launch_bounds__(BLOCK, 7) void es_fwd_kernel(
    const __grid_constant__ CUtensorMap tml,
    const __grid_constant__ CUtensorMap tms,
    const float* __restrict__ y,
    const int*   __restrict__ idxs,
    const float* __restrict__ lev_sms_p,
    const float* __restrict__ init_seas_p,
    float* __restrict__ out)
{
    __shared__ __align__(16) float ybuf[2][NWARP * YSTR];   // 7168
    __shared__ __align__(16) float ltile[2][NWARP * TSTR];  // 6144 (TMA src)
    __shared__ __align__(16) float stile[2][NWARP * TSTR];  // 6144 (TMA src)
    __shared__ __align__(16) float atile[2][NWARP * ASTR];  // 7168
    __shared__ __align__(16) float dtile[NWARP * DSTR];     // 3584 (also peel-y staging)
    __shared__ float llevH[2][NWARP];

    const int tid  = threadIdx.x;
    const int wid  = tid / 32;
    const int lane = tid & 31;
    const int s0   = blockIdx.x * NWARP;
    const int s    = s0 + lane;

    float* gl = out;
    float* gs = out + (size_t)NS * LEVW;
    float* gd = gs  + (size_t)NS * SEAW;

    const char* ybase = (const char*)(y + (size_t)s0 * NT);
    const int idx = idxs[s];
    // reference derives BOTH smoothing params from lev_sms (its own quirk)
    const float a   = 1.0f / (1.0f + __expf(-lev_sms_p[idx]));
    const float oma = 1.0f - a;
    const float* isr = init_seas_p + (size_t)idx * SEASK;

    float sv_[8], ar_[8], rsv0 = 0.0f, lev = 0.0f;   // W0 peel state

    // ======================= INIT (all warps) =======================
    if (wid == 1) {
        // G_peel: y[:,0:8) -> dtile (row stride 12 floats)
        #pragma unroll
        for (int j = 0; j < 2; j++) {
            const int f = lane + 32 * j;
            const int row = f >> 1, col = f & 1;
            cp16(smem_u32(dtile) + row * 48 + col * 16, ybase + row * (NT * 4) + col * 16);
        }
        cp_commit();
        // G_0: period 0 y -> ybuf[0]
        #pragma unroll
        for (int j = 0; j < 6; j++) {
            const int f = lane + 32 * j;
            const int row = f / 6, col = f % 6;
            cp16(smem_u32(ybuf[0]) + row * (YSTR * 4) + col * 16,
                 ybase + 32 + row * (NT * 4) + col * 16);
        }
        cp_commit();
        cp_wait<0>();
    }

    if (wid == 0) {
        // exps for pos 0..7 (peel state) + emit gs cols 0..7
        const float4 x0 = *(const float4*)(isr + 0);
        const float4 x1 = *(const float4*)(isr + 4);
        float4 e0, e1;
        e0.x = __expf(x0.x); e0.y = __expf(x0.y); e0.z = __expf(x0.z); e0.w = __expf(x0.w);
        e1.x = __expf(x1.x); e1.y = __expf(x1.y); e1.z = __expf(x1.z); e1.w = __expf(x1.w);
        sv_[0]=e0.x; sv_[1]=e0.y; sv_[2]=e0.z; sv_[3]=e0.w;
        sv_[4]=e1.x; sv_[5]=e1.y; sv_[6]=e1.z; sv_[7]=e1.w;
        ar_[0]=a*__expf(-x0.x); ar_[1]=a*__expf(-x0.y); ar_[2]=a*__expf(-x0.z); ar_[3]=a*__expf(-x0.w);
        ar_[4]=a*__expf(-x1.x); ar_[5]=a*__expf(-x1.y); ar_[6]=a*__expf(-x1.z); ar_[7]=a*__expf(-x1.w);
        rsv0 = __expf(-x0.x);
        float4* gsr = (float4*)(gs + (size_t)s * SEAW);
        __stcs(gsr + 0, e0); __stcs(gsr + 1, e1);
    } else {
        // W1a: pos 8..15 ; W1b: pos 16..23
        const int base = (wid == 1) ? 8 : 16;
        const float4 x0 = *(const float4*)(isr + base);
        const float4 x1 = *(const float4*)(isr + base + 4);
        float4 e0, e1, r0, r1;
        e0.x = __expf(x0.x); e0.y = __expf(x0.y); e0.z = __expf(x0.z); e0.w = __expf(x0.w);
        e1.x = __expf(x1.x); e1.y = __expf(x1.y); e1.z = __expf(x1.z); e1.w = __expf(x1.w);
        r0.x = a*__expf(-x0.x); r0.y = a*__expf(-x0.y); r0.z = a*__expf(-x0.z); r0.w = a*__expf(-x0.w);
        r1.x = a*__expf(-x1.x); r1.y = a*__expf(-x1.y); r1.z = a*__expf(-x1.z); r1.w = a*__expf(-x1.w);
        float4* gsr = (float4*)(gs + (size_t)s * SEAW + base);
        __stcs(gsr + 0, e0); __stcs(gsr + 1, e1);
        // seed period-0 input tiles: col k holds pos 8+k  ->  cols (base-8)..(base-1)
        float* sseed = stile[1] + lane * TSTR + (base - 8);
        float* aseed = atile[1] + lane * ASTR + (base - 8);
        *(float4*)(sseed) = e0; *(float4*)(sseed + 4) = e1;
        *(float4*)(aseed) = r0; *(float4*)(aseed + 4) = r1;
    }
    __syncthreads();   // B_init: peel-y + period0-y + tile seeds published

    // ======================= SLOT 0 =======================
    if (wid == 0) {
        // ---- peel steps 0..7 (y in dtile, stride 12) ----
        const float4 v0 = *(const float4*)(dtile + lane * 12);
        const float4 v1 = *(const float4*)(dtile + lane * 12 + 4);
        float yt[8] = {v0.x, v0.y, v0.z, v0.w, v1.x, v1.y, v1.z, v1.w};
        float q_[8], nl_[8], dt_[8];

        lev = yt[0] * rsv0;
        float llev = __logf(lev);
        nl_[0] = lev; dt_[0] = 0.0f;
        #pragma unroll
        for (int k = 1; k < 8; k++) q_[k] = yt[k] * ar_[k];
        #pragma unroll
        for (int k = 1; k < 8; k++) { nl_[k] = fmaf(oma, lev, q_[k]); lev = nl_[k]; }
        float ns_[8];
        #pragma unroll
        for (int k = 1; k < 8; k++)
            ns_[k] = fmaf(a, __fdividef(yt[k], nl_[k]), oma * sv_[k]);
        #pragma unroll
        for (int k = 1; k < 8; k++) {
            const float ll = __logf(nl_[k]);
            dt_[k] = ll - llev; llev = ll;
        }
        llevH[1][lane] = llev;   // carry for W1a's period 0

        // seed period-0 tiles cols 16..23 (pos 0 = init, pos 1..7 = peel-updated)
        float* sseed = stile[1] + lane * TSTR + 16;
        float* aseed = atile[1] + lane * ASTR + 16;
        *(float4*)(sseed)     = make_float4(sv_[0], ns_[1], ns_[2], ns_[3]);
        *(float4*)(sseed + 4) = make_float4(ns_[4], ns_[5], ns_[6], ns_[7]);
        *(float4*)(aseed)     = make_float4(a * rsv0, __fdividef(a, ns_[1]),
                                            __fdividef(a, ns_[2]), __fdividef(a, ns_[3]));
        *(float4*)(aseed + 4) = make_float4(__fdividef(a, ns_[4]), __fdividef(a, ns_[5]),
                                            __fdividef(a, ns_[6]), __fdividef(a, ns_[7]));

        // peel writeback staging (ltile[0]/stile[0] scratch, stride 8; dt in dtile)
        float* lb = ltile[0] + lane * 8;
        float* sb = stile[0] + lane * 8;
        float* db = dtile + lane * 12;
        *(float4*)(lb)     = make_float4(nl_[0], nl_[1], nl_[2], nl_[3]);
        *(float4*)(lb + 4) = make_float4(nl_[4], nl_[5], nl_[6], nl_[7]);
        *(float4*)(sb)     = make_float4(sv_[0], ns_[1], ns_[2], ns_[3]);
        *(float4*)(sb + 4) = make_float4(ns_[4], ns_[5], ns_[6], ns_[7]);
        *(float4*)(db)     = make_float4(dt_[0], dt_[1], dt_[2], dt_[3]);
        *(float4*)(db + 4) = make_float4(dt_[4], dt_[5], dt_[6], dt_[7]);
        __syncwarp();
        #pragma unroll
        for (int j = 0; j < 2; j++) {
            const int f = lane + 32 * j;
            const int row = f >> 1, qd = f & 1;
            __stcs((float4*)(gl + (size_t)(s0 + row) * LEVW) + qd,
                   ((const float4*)(ltile[0] + row * 8))[qd]);
            __stcs((float4*)(gs + (size_t)(s0 + row) * SEAW + SEASK) + qd,
                   ((const float4*)(stile[0] + row * 8))[qd]);
        }
        #pragma unroll
        for (int j = 0; j < 7; j++) {
            const int i = lane + 32 * j;
            const int row = i / 7, k = i % 7;
            gd[(size_t)(s0 + row) * LOGW + k] = dtile[row * 12 + 1 + k];
        }
        __syncwarp();

        // ---- period 0 compute -> tiles[0] (reads seeds in tiles[1]) ----
        const float* ysm  = ybuf[0] + lane * YSTR;
        const float* sold = stile[1] + lane * TSTR;
        const float* aold = atile[1] + lane * ASTR;
        half12(ysm,      sold,      aold,      ltile[0] + lane*TSTR,      stile[0] + lane*TSTR,      atile[0] + lane*ASTR,      a, oma, lev);
        half12(ysm + 12, sold + 12, aold + 12, ltile[0] + lane*TSTR + 12, stile[0] + lane*TSTR + 12, atile[0] + lane*ASTR + 12, a, oma, lev);
    } else if (wid == 1) {
        // G_1 prefetch
        #pragma unroll
        for (int j = 0; j < 6; j++) {
            const int f = lane + 32 * j;
            const int row = f / 6, col = f % 6;
            cp16(smem_u32(ybuf[1]) + row * (YSTR * 4) + col * 16,
                 ybase + 32 + 96 + row * (NT * 4) + col * 16);
        }
        cp_commit();
        cp_wait<0>();
    }
    __syncthreads();   // B_0

    // ======================= STEADY SLOTS 1..21 =======================
    #pragma unroll 1
    for (int slot = 1; slot <= NPER; slot++) {
        if (wid == 0) {
            if (slot <= NPER - 1) {
                const int p = slot;
                const float* ysm  = ybuf[p & 1] + lane * YSTR;
                const float* sold = stile[(p & 1) ^ 1] + lane * TSTR;
                const float* aold = atile[(p & 1) ^ 1] + lane * ASTR;
                float* lnew = ltile[p & 1] + lane * TSTR;
                float* snew = stile[p & 1] + lane * TSTR;
                float* anew = atile[p & 1] + lane * ASTR;
                half12(ysm,      sold,      aold,      lnew,      snew,      anew,      a, oma, lev);
                half12(ysm + 12, sold + 12, aold + 12, lnew + 12, snew + 12, anew + 12, a, oma, lev);
            }
        } else if (wid == 1) {
            // prefetch y for period slot+1 (if it exists)
            if (slot <= NPER - 2) {
                const char* yb = ybase + 32 + (size_t)(slot + 1) * 96;
                const unsigned d = smem_u32(ybuf[(slot + 1) & 1]);
                #pragma unroll
                for (int j = 0; j < 6; j++) {
                    const int f = lane + 32 * j;
                    const int row = f / 6, col = f % 6;
                    cp16(d + row * (YSTR * 4) + col * 16, yb + row * (NT * 4) + col * 16);
                }
                cp_commit();
                cp_wait<0>();
            }
            // logs/gd for period P = slot-1, columns 0..11
            const int P  = slot - 1;
            const int b  = P & 1;
            const int tp = 8 + 24 * P;
            float llev = llevH[b ^ 1][lane];
            loghalf(ltile[b] + lane * TSTR, dtile + lane * DSTR, llev);
            __syncwarp();
            #pragma unroll
            for (int j = 0; j < 12; j++) {
                const int i = lane + 32 * j;
                const int row = i / 12, k = i % 12;
                gd[(size_t)(s0 + row) * LOGW + tp - 1 + k] = dtile[row * DSTR + k];
            }
        } else {
            // W1b: TMA + logs/gd for period P = slot-1, columns 12..23
            const int P  = slot - 1;
            const int b  = P & 1;
            const int tp = 8 + 24 * P;
            if (lane == 0) {
                fence_async_shared();
                tma_store2d(&tml, tp,         s0, smem_u32(ltile[b]));
                tma_store2d(&tms, tp + SEASK, s0, smem_u32(stile[b]));
                bulk_commit();
            }
            const float* nlrow = ltile[b] + lane * TSTR;
            const float base = __logf(nlrow[11]);            // boundary (redundant)
            const float llast = loghalf(nlrow + 12, dtile + lane * DSTR + 12, base);
            llevH[b][lane] = llast;                          // carry for next period's W1a
            __syncwarp();
            #pragma unroll
            for (int j = 0; j < 12; j++) {
                const int i = lane + 32 * j;
                const int row = i / 12, k = 12 + i % 12;
                gd[(size_t)(s0 + row) * LOGW + tp - 1 + k] = dtile[row * DSTR + k];
            }
            if (lane == 0) bulk_wait<0>();   // tiles[b] drained before W0 reuses at slot+1
        }
        __syncthreads();
    }
}

extern "C" void kernel_launch(void* const* d_in, const int* in_sizes, int n_in,
                              void* d_out, int out_size)
{
    const float* y         = (const float*)d_in[0];
    const int*   idxs      = (const int*)  d_in[1];
    const float* lev_sms   = (const float*)d_in[2];
    const float* init_seas = (const float*)d_in[4];  // d_in[3] unused (reference quirk)
    float* out = (float*)d_out;

    typedef CUresult (*EncodeFn)(CUtensorMap*, CUtensorMapDataType, cuuint32_t, void*,
                                 const cuuint64_t*, const cuuint64_t*, const cuuint32_t*,
                                 const cuuint32_t*, CUtensorMapInterleave, CUtensorMapSwizzle,
                                 CUtensorMapL2promotion, CUtensorMapFloatOOBfill);
    EncodeFn enc = nullptr;
    cudaDriverEntryPointQueryResult qr;
    cudaGetDriverEntryPointByVersion("cuTensorMapEncodeTiled", (void**)&enc, 12000,
                                     cudaEnableDefault, &qr);

    CUtensorMap tml, tms;
    {
        cuuint64_t dims[2]    = { (cuuint64_t)LEVW, (cuuint64_t)NS };
        cuuint64_t strides[1] = { (cuuint64_t)LEVW * 4 };
        cuuint32_t box[2]     = { 24, 32 };
        cuuint32_t es[2]      = { 1, 1 };
        enc(&tml, CU_TENSOR_MAP_DATA_TYPE_FLOAT32, 2, out, dims, strides, box, es,
            CU_TENSOR_MAP_INTERLEAVE_NONE, CU_TENSOR_MAP_SWIZZLE_NONE,
            CU_TENSOR_MAP_L2_PROMOTION_L2_128B, CU_TENSOR_MAP_FLOAT_OOB_FILL_NONE);
    }
    {
        float* gsp = out + (size_t)NS * LEVW;
        cuuint64_t dims[2]    = { (cuuint64_t)SEAW, (cuuint64_t)NS };
        cuuint64_t strides[1] = { (cuuint64_t)SEAW * 4 };
        cuuint32_t box[2]     = { 24, 32 };
        cuuint32_t es[2]      = { 1, 1 };
        enc(&tms, CU_TENSOR_MAP_DATA_TYPE_FLOAT32, 2, gsp, dims, strides, box, es,
            CU_TENSOR_MAP_INTERLEAVE_NONE, CU_TENSOR_MAP_SWIZZLE_NONE,
            CU_TENSOR_MAP_L2_PROMOTION_L2_128B, CU_TENSOR_MAP_FLOAT_OOB_FILL_NONE);
    }

    es_fwd_kernel<<<NS / NWARP, BLOCK>>>(tml, tms, y, idxs, lev_sms, init_seas, out);
}

// round 13
// speedup vs baseline: 1.1222x; 1.1222x over previous
#include <cuda_runtime.h>
#include <cuda.h>

#define NS      32768
#define NT      512
#define SEASK   24
#define LEVW    512
#define SEAW    536
#define LOGW    511

#define NWARP   32          // series per block
#define BLOCK   64          // two symmetric warps, ping-pong compute/IO
#define NPER    21          // periods of 24 steps, t = 8..511
#define YSTR    28          // y smem row stride (conflict-free .128)
#define TSTR    24          // TMA tile row stride (packed)
#define DSTR    28          // dtile row stride

__device__ __forceinline__ unsigned smem_u32(const void* p) {
    return (unsigned)__cvta_generic_to_shared(p);
}
__device__ __forceinline__ void cp16(unsigned dst, const void* src) {
    asm volatile("cp.async.cg.shared.global [%0], [%1], 16;\n" :: "r"(dst), "l"(src) : "memory");
}
__device__ __forceinline__ void cp_commit() {
    asm volatile("cp.async.commit_group;\n" ::: "memory");
}
template<int N> __device__ __forceinline__ void cp_wait() {
    asm volatile("cp.async.wait_group %0;\n" :: "n"(N) : "memory");
}
__device__ __forceinline__ void tma_store2d(const void* map, int x, int y, unsigned smem) {
    asm volatile("cp.async.bulk.tensor.2d.global.shared::cta.tile.bulk_group [%0, {%1, %2}], [%3];"
                 :: "l"(map), "r"(x), "r"(y), "r"(smem) : "memory");
}
__device__ __forceinline__ void bulk_commit() {
    asm volatile("cp.async.bulk.commit_group;" ::: "memory");
}
template<int N> __device__ __forceinline__ void bulk_wait() {
    asm volatile("cp.async.bulk.wait_group %0;" :: "n"(N) : "memory");
}
__device__ __forceinline__ void fence_async_shared() {
    asm volatile("fence.proxy.async.shared::cta;" ::: "memory");
}

// 12 recurrence steps. sold column k = seasonal value of slot (8+k)%24 as of
// the previous period (i.e. the value from exactly 24 steps before its use).
__device__ __forceinline__ void half12(
    const float* __restrict__ ysm, const float* __restrict__ sold,
    float* __restrict__ lnew, float* __restrict__ snew,
    float a, float oma, float& lev)
{
    float yt[12], sv[12], q_[12], nl_[12];
    #pragma unroll
    for (int m = 0; m < 3; m++) {
        const float4 v = *(const float4*)(ysm  + 4 * m);
        const float4 w = *(const float4*)(sold + 4 * m);
        yt[4*m+0] = v.x; yt[4*m+1] = v.y; yt[4*m+2] = v.z; yt[4*m+3] = v.w;
        sv[4*m+0] = w.x; sv[4*m+1] = w.y; sv[4*m+2] = w.z; sv[4*m+3] = w.w;
    }
    #pragma unroll
    for (int k = 0; k < 12; k++) q_[k] = a * __fdividef(yt[k], sv[k]);
    #pragma unroll
    for (int k = 0; k < 12; k++) { nl_[k] = fmaf(oma, lev, q_[k]); lev = nl_[k]; }
    #pragma unroll
    for (int m = 0; m < 3; m++) {
        const float n0 = fmaf(a, __fdividef(yt[4*m+0], nl_[4*m+0]), oma * sv[4*m+0]);
        const float n1 = fmaf(a, __fdividef(yt[4*m+1], nl_[4*m+1]), oma * sv[4*m+1]);
        const float n2 = fmaf(a, __fdividef(yt[4*m+2], nl_[4*m+2]), oma * sv[4*m+2]);
        const float n3 = fmaf(a, __fdividef(yt[4*m+3], nl_[4*m+3]), oma * sv[4*m+3]);
        *(float4*)(snew + 4*m) = make_float4(n0, n1, n2, n3);
        *(float4*)(lnew + 4*m) = make_float4(nl_[4*m+0], nl_[4*m+1], nl_[4*m+2], nl_[4*m+3]);
    }
}

__global__ __launch_bounds__(BLOCK, 7) void es_fwd_kernel(
    const __grid_constant__ CUtensorMap tml,
    const __grid_constant__ CUtensorMap tms,
    const float* __restrict__ y,
    const int*   __restrict__ idxs,
    const float* __restrict__ lev_sms_p,
    const float* __restrict__ init_seas_p,
    float* __restrict__ out)
{
    __shared__ __align__(16) float ybufW[2][NWARP * YSTR];  // per-warp y staging
    __shared__ __align__(16) float y0buf[NWARP * 12];       // peel y
    __shared__ __align__(16) float ltile[2][NWARP * TSTR];  // TMA src (levels)
    __shared__ __align__(16) float stile[2][NWARP * TSTR];  // TMA src (seas) + state carry
    __shared__ __align__(16) float dtile[NWARP * DSTR];     // IO scratch (alternating warps)
    __shared__ float levb[2][NWARP];
    __shared__ float llevb[NWARP];

    const int tid  = threadIdx.x;
    const int wid  = tid >> 5;
    const int lane = tid & 31;
    const int s0   = blockIdx.x * NWARP;
    const int s    = s0 + lane;

    float* gl = out;
    float* gs = out + (size_t)NS * LEVW;
    float* gd = gs  + (size_t)NS * SEAW;

    const char* ybase = (const char*)(y + (size_t)s0 * NT);
    const int idx = idxs[s];
    // reference derives BOTH smoothing params from lev_sms (its own quirk)
    const float a   = 1.0f / (1.0f + __expf(-lev_sms_p[idx]));
    const float oma = 1.0f - a;
    const float* isr = init_seas_p + (size_t)idx * SEASK;

    float sv_[8], rsv0 = 0.0f;   // W0 peel state

    // ======================= INIT =======================
    if (wid == 1) {
        // group A: peel y (steps 0..7) + period-0 y  (needed by W0 at iter 0)
        #pragma unroll
        for (int j = 0; j < 2; j++) {
            const int f = lane + 32 * j;
            const int row = f >> 1, col = f & 1;
            cp16(smem_u32(y0buf) + row * 48 + col * 16, ybase + row * (NT * 4) + col * 16);
        }
        #pragma unroll
        for (int j = 0; j < 6; j++) {
            const int f = lane + 32 * j;
            const int row = f / 6, col = f % 6;
            cp16(smem_u32(ybufW[0]) + row * (YSTR * 4) + col * 16,
                 ybase + 32 + row * (NT * 4) + col * 16);
        }
        cp_commit();
        // group B: period-1 y (W1's own first compute)
        #pragma unroll
        for (int j = 0; j < 6; j++) {
            const int f = lane + 32 * j;
            const int row = f / 6, col = f % 6;
            cp16(smem_u32(ybufW[1]) + row * (YSTR * 4) + col * 16,
                 ybase + 32 + 96 + row * (NT * 4) + col * 16);
        }
        cp_commit();
        cp_wait<1>();   // group A done before B_init (group B waits at compute(1))

        // seed stile[1] cols 0..15 = exp(init) for pos 8..23; emit gs cols 8..23
        #pragma unroll
        for (int h = 0; h < 2; h++) {
            const int base = 8 + 8 * h;
            const float4 x0 = *(const float4*)(isr + base);
            const float4 x1 = *(const float4*)(isr + base + 4);
            float4 e0, e1;
            e0.x = __expf(x0.x); e0.y = __expf(x0.y); e0.z = __expf(x0.z); e0.w = __expf(x0.w);
            e1.x = __expf(x1.x); e1.y = __expf(x1.y); e1.z = __expf(x1.z); e1.w = __expf(x1.w);
            float4* gsr = (float4*)(gs + (size_t)s * SEAW + base);
            __stcs(gsr + 0, e0); __stcs(gsr + 1, e1);
            float* sd = stile[1] + lane * TSTR + 8 * h;
            *(float4*)(sd) = e0; *(float4*)(sd + 4) = e1;
        }
    } else {
        // W0: exps for pos 0..7; emit gs cols 0..7
        const float4 x0 = *(const float4*)(isr + 0);
        const float4 x1 = *(const float4*)(isr + 4);
        float4 e0, e1;
        e0.x = __expf(x0.x); e0.y = __expf(x0.y); e0.z = __expf(x0.z); e0.w = __expf(x0.w);
        e1.x = __expf(x1.x); e1.y = __expf(x1.y); e1.z = __expf(x1.z); e1.w = __expf(x1.w);
        sv_[0]=e0.x; sv_[1]=e0.y; sv_[2]=e0.z; sv_[3]=e0.w;
        sv_[4]=e1.x; sv_[5]=e1.y; sv_[6]=e1.z; sv_[7]=e1.w;
        rsv0 = __expf(-x0.x);
        float4* gsr = (float4*)(gs + (size_t)s * SEAW);
        __stcs(gsr + 0, e0); __stcs(gsr + 1, e1);
    }
    __syncthreads();   // B_init

    float lev = 0.0f;

    // ================= iterations: iter p computes period p (owner),
    // ================= while the peer does IO for period p-1 =================
    #pragma unroll 1
    for (int iter = 0; iter <= NPER; iter++) {
        const bool own_compute = (iter < NPER) && ((iter & 1) == wid);
        const bool own_io      = (iter >= 1) && (((iter - 1) & 1) == wid);

        if (own_compute) {
            bulk_wait<0>();   // my TMA from period iter-2 (committed ~1 iter ago)
            cp_wait<0>();     // my y group for this period

            if (iter == 0) {
                // ---- peel steps 0..7 ----
                const float4 v0 = *(const float4*)(y0buf + lane * 12);
                const float4 v1 = *(const float4*)(y0buf + lane * 12 + 4);
                float yt[8] = {v0.x, v0.y, v0.z, v0.w, v1.x, v1.y, v1.z, v1.w};
                float q_[8], nl_[8], dt_[8], ns_[8];

                lev = yt[0] * rsv0;
                float llev = __logf(lev);
                nl_[0] = lev; dt_[0] = 0.0f;
                #pragma unroll
                for (int k = 1; k < 8; k++) q_[k] = a * __fdividef(yt[k], sv_[k]);
                #pragma unroll
                for (int k = 1; k < 8; k++) { nl_[k] = fmaf(oma, lev, q_[k]); lev = nl_[k]; }
                #pragma unroll
                for (int k = 1; k < 8; k++)
                    ns_[k] = fmaf(a, __fdividef(yt[k], nl_[k]), oma * sv_[k]);
                #pragma unroll
                for (int k = 1; k < 8; k++) {
                    const float ll = __logf(nl_[k]);
                    dt_[k] = ll - llev; llev = ll;
                }
                llevb[lane] = llev;     // seed for IO(0)

                // seed stile[1] cols 16..23 (pos 0 = init, pos 1..7 = peel output)
                float* sd = stile[1] + lane * TSTR + 16;
                *(float4*)(sd)     = make_float4(sv_[0], ns_[1], ns_[2], ns_[3]);
                *(float4*)(sd + 4) = make_float4(ns_[4], ns_[5], ns_[6], ns_[7]);

                // peel writeback via dtile scratch (l:0-7, s:8-15, d:16-23)
                float* pb = dtile + lane * DSTR;
                *(float4*)(pb +  0) = make_float4(nl_[0], nl_[1], nl_[2], nl_[3]);
                *(float4*)(pb +  4) = make_float4(nl_[4], nl_[5], nl_[6], nl_[7]);
                *(float4*)(pb +  8) = make_float4(sv_[0], ns_[1], ns_[2], ns_[3]);
                *(float4*)(pb + 12) = make_float4(ns_[4], ns_[5], ns_[6], ns_[7]);
                *(float4*)(pb + 16) = make_float4(dt_[0], dt_[1], dt_[2], dt_[3]);
                *(float4*)(pb + 20) = make_float4(dt_[4], dt_[5], dt_[6], dt_[7]);
                __syncwarp();
                #pragma unroll
                for (int j = 0; j < 2; j++) {
                    const int f = lane + 32 * j;
                    const int row = f >> 1, qd = f & 1;
                    __stcs((float4*)(gl + (size_t)(s0 + row) * LEVW) + qd,
                           ((const float4*)(dtile + row * DSTR))[qd]);
                    __stcs((float4*)(gs + (size_t)(s0 + row) * SEAW + SEASK) + qd,
                           ((const float4*)(dtile + row * DSTR + 8))[qd]);
                }
                #pragma unroll
                for (int j = 0; j < 7; j++) {
                    const int i = lane + 32 * j;
                    const int row = i / 7, k = i % 7;
                    __stcs(gd + (size_t)(s0 + row) * LOGW + k, dtile[row * DSTR + 17 + k]);
                }
                __syncwarp();
            } else {
                lev = levb[(iter - 1) & 1][lane];   // carry from peer
            }

            // ---- compute period `iter` ----
            const int b = iter & 1;
            const float* ysm  = ybufW[wid] + lane * YSTR;
            const float* sold = stile[b ^ 1] + lane * TSTR;
            float* lnew = ltile[b] + lane * TSTR;
            float* snew = stile[b] + lane * TSTR;
            half12(ysm,      sold,      lnew,      snew,      a, oma, lev);
            half12(ysm + 12, sold + 12, lnew + 12, snew + 12, a, oma, lev);
            levb[b][lane] = lev;
        } else if (own_io) {
            const int P  = iter - 1;
            const int b  = P & 1;
            const int tp = 8 + 24 * P;

            // prefetch y for my next compute period (P+2)
            if (P + 2 < NPER) {
                const char* yb = ybase + 32 + (size_t)(P + 2) * 96;
                const unsigned d = smem_u32(ybufW[wid]);
                #pragma unroll
                for (int j = 0; j < 6; j++) {
                    const int f = lane + 32 * j;
                    const int row = f / 6, col = f % 6;
                    cp16(d + row * (YSTR * 4) + col * 16, yb + row * (NT * 4) + col * 16);
                }
                cp_commit();   // waited at my next compute, ~1 iteration later
            }

            // TMA for period P (tiles written by ME last iteration)
            if (lane == 0) {
                fence_async_shared();
                tma_store2d(&tml, tp,         s0, smem_u32(ltile[b]));
                tma_store2d(&tms, tp + SEASK, s0, smem_u32(stile[b]));
                bulk_commit();
            }

            // logs + diffs for period P
            float llev = llevb[lane];
            const float* nlrow = ltile[b] + lane * TSTR;
            float* db = dtile + lane * DSTR;
            #pragma unroll
            for (int m = 0; m < 6; m++) {
                const float4 v = *(const float4*)(nlrow + 4 * m);
                const float l0 = __logf(v.x), l1 = __logf(v.y);
                const float l2 = __logf(v.z), l3 = __logf(v.w);
                *(float4*)(db + 4 * m) = make_float4(l0 - llev, l1 - l0, l2 - l1, l3 - l2);
                llev = l3;
            }
            llevb[lane] = llev;
            __syncwarp();

            // gd: coalesced scalar stores from transposed scratch
            #pragma unroll
            for (int j = 0; j < 24; j++) {
                const int i = lane + 32 * j;
                const int row = i / 24, k = i % 24;
                __stcs(gd + (size_t)(s0 + row) * LOGW + tp - 1 + k, dtile[row * DSTR + k]);
            }
        }
        __syncthreads();
    }

    if (lane == 0) bulk_wait<0>();   // smem must outlive pending TMA
}

extern "C" void kernel_launch(void* const* d_in, const int* in_sizes, int n_in,
                              void* d_out, int out_size)
{
    const float* y         = (const float*)d_in[0];
    const int*   idxs      = (const int*)  d_in[1];
    const float* lev_sms   = (const float*)d_in[2];
    const float* init_seas = (const float*)d_in[4];  // d_in[3] unused (reference quirk)
    float* out = (float*)d_out;

    typedef CUresult (*EncodeFn)(CUtensorMap*, CUtensorMapDataType, cuuint32_t, void*,
                                 const cuuint64_t*, const cuuint64_t*, const cuuint32_t*,
                                 const cuuint32_t*, CUtensorMapInterleave, CUtensorMapSwizzle,
                                 CUtensorMapL2promotion, CUtensorMapFloatOOBfill);
    EncodeFn enc = nullptr;
    cudaDriverEntryPointQueryResult qr;
    cudaGetDriverEntryPointByVersion("cuTensorMapEncodeTiled", (void**)&enc, 12000,
                                     cudaEnableDefault, &qr);

    CUtensorMap tml, tms;
    {
        cuuint64_t dims[2]    = { (cuuint64_t)LEVW, (cuuint64_t)NS };
        cuuint64_t strides[1] = { (cuuint64_t)LEVW * 4 };
        cuuint32_t box[2]     = { 24, 32 };
        cuuint32_t es[2]      = { 1, 1 };
        enc(&tml, CU_TENSOR_MAP_DATA_TYPE_FLOAT32, 2, out, dims, strides, box, es,
            CU_TENSOR_MAP_INTERLEAVE_NONE, CU_TENSOR_MAP_SWIZZLE_NONE,
            CU_TENSOR_MAP_L2_PROMOTION_L2_128B, CU_TENSOR_MAP_FLOAT_OOB_FILL_NONE);
    }
    {
        float* gsp = out + (size_t)NS * LEVW;
        cuuint64_t dims[2]    = { (cuuint64_t)SEAW, (cuuint64_t)NS };
        cuuint64_t strides[1] = { (cuuint64_t)SEAW * 4 };
        cuuint32_t box[2]     = { 24, 32 };
        cuuint32_t es[2]      = { 1, 1 };
        enc(&tms, CU_TENSOR_MAP_DATA_TYPE_FLOAT32, 2, gsp, dims, strides, box, es,
            CU_TENSOR_MAP_INTERLEAVE_NONE, CU_TENSOR_MAP_SWIZZLE_NONE,
            CU_TENSOR_MAP_L2_PROMOTION_L2_128B, CU_TENSOR_MAP_FLOAT_OOB_FILL_NONE);
    }

    es_fwd_kernel<<<NS / NWARP, BLOCK>>>(tml, tms, y, idxs, lev_sms, init_seas, out);
}